// round 3
// baseline (speedup 1.0000x reference)
#include <cuda_runtime.h>

// Problem constants
#define POOL 7
#define NUM_ROIS 256
#define H_IMG 128
#define W_IMG 128
#define C_IMG 1024
#define SCALE (1.0f / 16.0f)

// One CTA per (roi, cell), 256 threads, one float4 of channels per thread.
// L2-bandwidth-bound kernel: skip corner loads that are algebraically dead
// (tx==0 / ty==0 => lerp weight zero; clamped coords => duplicate pixel).
// Conditions are uniform per CTA -> no divergence.
__global__ void __launch_bounds__(256, 8)
roi_pool_kernel(const float* __restrict__ img,
                const float* __restrict__ rois,
                float* __restrict__ out)
{
    const int cell = blockIdx.x;   // 0..48
    const int roi  = blockIdx.y;   // 0..255
    const int iy   = cell / POOL;
    const int ix   = cell % POOL;

    const float4 r = *(const float4*)(rois + roi * 4);
    const int x0 = (int)(r.x * SCALE);
    const int y0 = (int)(r.y * SCALE);
    const int w  = (int)(r.z * SCALE);
    const int h  = (int)(r.w * SCALE);

    // Match reference arithmetic order exactly
    const float sy = (float)iy * ((float)h / (float)POOL);
    const float sx = (float)ix * ((float)w / (float)POOL);
    const float fy = floorf(sy);
    const float fx = floorf(sx);
    const float ty = sy - fy;
    const float tx = sx - fx;
    const int y_lo = (int)fy;
    const int x_lo = (int)fx;
    const int y_hi = min(y_lo + 1, max(h - 1, 0));
    const int x_hi = min(x_lo + 1, max(w - 1, 0));
    const int gy0 = min(max(y0 + y_lo, 0), H_IMG - 1);
    const int gy1 = min(max(y0 + y_hi, 0), H_IMG - 1);
    const int gx0 = min(max(x0 + x_lo, 0), W_IMG - 1);
    const int gx1 = min(max(x0 + x_hi, 0), W_IMG - 1);

    // Dead-load elimination flags (uniform across the CTA).
    //  tx==0      -> x-lerp contributes 0 exactly; v01/v11 unused.
    //  gx1==gx0   -> v01 is the same pixel as v00; tx*(v01-v00)=tx*0=0 exactly.
    const bool needx = (tx != 0.0f) && (gx1 != gx0);
    const bool needy = (ty != 0.0f) && (gy1 != gy0);

    const int c = threadIdx.x;  // float4 index 0..255

    const float4* p00 = (const float4*)(img + ((size_t)(gy0 * W_IMG + gx0) << 10));
    const float4* p01 = (const float4*)(img + ((size_t)(gy0 * W_IMG + gx1) << 10));
    const float4* p10 = (const float4*)(img + ((size_t)(gy1 * W_IMG + gx0) << 10));
    const float4* p11 = (const float4*)(img + ((size_t)(gy1 * W_IMG + gx1) << 10));

    float4 o;

    if (needx & needy) {
        const float4 v00 = p00[c];
        const float4 v01 = p01[c];
        const float4 v10 = p10[c];
        const float4 v11 = p11[c];
        {
            float top = v00.x + tx * (v01.x - v00.x);
            float bot = v10.x + tx * (v11.x - v10.x);
            o.x = top + ty * (bot - top);
        }
        {
            float top = v00.y + tx * (v01.y - v00.y);
            float bot = v10.y + tx * (v11.y - v10.y);
            o.y = top + ty * (bot - top);
        }
        {
            float top = v00.z + tx * (v01.z - v00.z);
            float bot = v10.z + tx * (v11.z - v10.z);
            o.z = top + ty * (bot - top);
        }
        {
            float top = v00.w + tx * (v01.w - v00.w);
            float bot = v10.w + tx * (v11.w - v10.w);
            o.w = top + ty * (bot - top);
        }
    } else if (needy) {
        // x-lerp is identity: out = v00 + ty*(v10 - v00)
        const float4 v00 = p00[c];
        const float4 v10 = p10[c];
        o.x = v00.x + ty * (v10.x - v00.x);
        o.y = v00.y + ty * (v10.y - v00.y);
        o.z = v00.z + ty * (v10.z - v00.z);
        o.w = v00.w + ty * (v10.w - v00.w);
    } else if (needx) {
        // y-lerp is identity: out = v00 + tx*(v01 - v00)
        const float4 v00 = p00[c];
        const float4 v01 = p01[c];
        o.x = v00.x + tx * (v01.x - v00.x);
        o.y = v00.y + tx * (v01.y - v00.y);
        o.z = v00.z + tx * (v01.z - v00.z);
        o.w = v00.w + tx * (v01.w - v00.w);
    } else {
        o = p00[c];
    }

    float4* out4 = (float4*)out;
    out4[((size_t)(roi * (POOL * POOL) + cell) << 8) + c] = o;
}

extern "C" void kernel_launch(void* const* d_in, const int* in_sizes, int n_in,
                              void* d_out, int out_size)
{
    const float* img  = (const float*)d_in[0];
    const float* rois = (const float*)d_in[1];
    float* out = (float*)d_out;

    dim3 grid(POOL * POOL, NUM_ROIS);
    roi_pool_kernel<<<grid, 256>>>(img, rois, out);
}

// round 4
// speedup vs baseline: 1.3720x; 1.3720x over previous
#include <cuda_runtime.h>

// Problem constants
#define POOL 7
#define NUM_ROIS 256
#define H_IMG 128
#define W_IMG 128
#define C_IMG 1024
#define SCALE (1.0f / 16.0f)

// One CTA per (roi, cell-row iy). 256 threads, one float4 channel chunk per
// thread, looping over the 7 cells (ix) of the row. Adjacent cells share
// corner pixels (gy0/gy1 identical across the row; gx values overlap), so
// repeated loads hit this SM's L1 instead of burning L2 bandwidth — the
// kernel is L2-BW capped (~12.4 TB/s measured).
// Straight-line unrolled, loads batched per cell: no branch overhead.
__global__ void __launch_bounds__(256, 8)
roi_pool_kernel(const float* __restrict__ img,
                const float* __restrict__ rois,
                float* __restrict__ out)
{
    const int iy  = blockIdx.x;   // 0..6
    const int roi = blockIdx.y;   // 0..255

    const float4 r = *(const float4*)(rois + roi * 4);
    const int x0 = (int)(r.x * SCALE);
    const int y0 = (int)(r.y * SCALE);
    const int w  = (int)(r.z * SCALE);
    const int h  = (int)(r.w * SCALE);

    // y-side (shared by all 7 cells of this row) — match reference order
    const float sy = (float)iy * ((float)h / (float)POOL);
    const float fy = floorf(sy);
    const float ty = sy - fy;
    const int y_lo = (int)fy;
    const int y_hi = min(y_lo + 1, max(h - 1, 0));
    const int gy0 = min(max(y0 + y_lo, 0), H_IMG - 1);
    const int gy1 = min(max(y0 + y_hi, 0), H_IMG - 1);

    const float* row0 = img + ((size_t)(gy0 * W_IMG) << 10);
    const float* row1 = img + ((size_t)(gy1 * W_IMG) << 10);

    const int c = threadIdx.x;  // float4 index 0..255
    float4* out4 = (float4*)out;
    const size_t obase = (((size_t)(roi * POOL + iy) * POOL) << 8) + c;

    const float xstep = (float)w / (float)POOL;
    const int hx_cap = max(w - 1, 0);

    #pragma unroll
    for (int ix = 0; ix < POOL; ix++) {
        const float sx = (float)ix * xstep;
        const float fx = floorf(sx);
        const float tx = sx - fx;
        const int x_lo = (int)fx;
        const int x_hi = min(x_lo + 1, hx_cap);
        const int gx0 = min(max(x0 + x_lo, 0), W_IMG - 1);
        const int gx1 = min(max(x0 + x_hi, 0), W_IMG - 1);

        const float4 v00 = ((const float4*)(row0 + ((size_t)gx0 << 10)))[c];
        const float4 v01 = ((const float4*)(row0 + ((size_t)gx1 << 10)))[c];
        const float4 v10 = ((const float4*)(row1 + ((size_t)gx0 << 10)))[c];
        const float4 v11 = ((const float4*)(row1 + ((size_t)gx1 << 10)))[c];

        float4 o;
        {
            float top = v00.x + tx * (v01.x - v00.x);
            float bot = v10.x + tx * (v11.x - v10.x);
            o.x = top + ty * (bot - top);
        }
        {
            float top = v00.y + tx * (v01.y - v00.y);
            float bot = v10.y + tx * (v11.y - v10.y);
            o.y = top + ty * (bot - top);
        }
        {
            float top = v00.z + tx * (v01.z - v00.z);
            float bot = v10.z + tx * (v11.z - v10.z);
            o.z = top + ty * (bot - top);
        }
        {
            float top = v00.w + tx * (v01.w - v00.w);
            float bot = v10.w + tx * (v11.w - v10.w);
            o.w = top + ty * (bot - top);
        }

        out4[obase + ((size_t)ix << 8)] = o;
    }
}

extern "C" void kernel_launch(void* const* d_in, const int* in_sizes, int n_in,
                              void* d_out, int out_size)
{
    const float* img  = (const float*)d_in[0];
    const float* rois = (const float*)d_in[1];
    float* out = (float*)d_out;

    dim3 grid(POOL, NUM_ROIS);
    roi_pool_kernel<<<grid, 256>>>(img, rois, out);
}

// round 6
// speedup vs baseline: 1.3908x; 1.0137x over previous
#include <cuda_runtime.h>

// Problem constants
#define POOL 7
#define NUM_ROIS 256
#define H_IMG 128
#define W_IMG 128
#define C_IMG 1024
#define SCALE (1.0f / 16.0f)

// One CTA per (roi, cell), 256 threads, one float4 of channels per thread.
// Kernel is pinned at the LTS (L2) bandwidth cap (~12.4 TB/s). We cut L2
// read bytes ~25% branchlessly: when a lerp weight is exactly zero, the
// corresponding corner load is algebraically dead — instead of skipping it
// (branches killed R3), we redirect its ADDRESS to the live corner via SEL.
// The load becomes a same-line L1 hit (zero L2/DRAM bytes) and the result
// is bit-identical: v + 0*(x - v) == v for any finite x.
__global__ void __launch_bounds__(256, 8)
roi_pool_kernel(const float* __restrict__ img,
                const float* __restrict__ rois,
                float* __restrict__ out)
{
    const int cell = blockIdx.x;   // 0..48
    const int roi  = blockIdx.y;   // 0..255
    const int iy   = cell / POOL;
    const int ix   = cell % POOL;

    const float4 r = *(const float4*)(rois + roi * 4);
    const int x0 = (int)(r.x * SCALE);
    const int y0 = (int)(r.y * SCALE);
    const int w  = (int)(r.z * SCALE);
    const int h  = (int)(r.w * SCALE);

    // Match reference arithmetic order exactly
    const float sy = (float)iy * ((float)h / (float)POOL);
    const float sx = (float)ix * ((float)w / (float)POOL);
    const float fy = floorf(sy);
    const float fx = floorf(sx);
    const float ty = sy - fy;
    const float tx = sx - fx;
    const int y_lo = (int)fy;
    const int x_lo = (int)fx;
    const int y_hi = min(y_lo + 1, max(h - 1, 0));
    const int x_hi = min(x_lo + 1, max(w - 1, 0));
    const int gy0 = min(max(y0 + y_lo, 0), H_IMG - 1);
    int       gy1 = min(max(y0 + y_hi, 0), H_IMG - 1);
    const int gx0 = min(max(x0 + x_lo, 0), W_IMG - 1);
    int       gx1 = min(max(x0 + x_hi, 0), W_IMG - 1);

    // Branchless dead-load redirection (SEL, no BSSY/BSYNC):
    // weight==0  =>  point the dead corner at the live one (L1-hit alias).
    gx1 = (tx != 0.0f) ? gx1 : gx0;
    gy1 = (ty != 0.0f) ? gy1 : gy0;

    const float4* p00 = (const float4*)(img + ((size_t)(gy0 * W_IMG + gx0) << 10));
    const float4* p01 = (const float4*)(img + ((size_t)(gy0 * W_IMG + gx1) << 10));
    const float4* p10 = (const float4*)(img + ((size_t)(gy1 * W_IMG + gx0) << 10));
    const float4* p11 = (const float4*)(img + ((size_t)(gy1 * W_IMG + gx1) << 10));

    const int c = threadIdx.x;  // float4 index 0..255

    const float4 v00 = p00[c];
    const float4 v01 = p01[c];
    const float4 v10 = p10[c];
    const float4 v11 = p11[c];

    float4 o;
    {
        float top = v00.x + tx * (v01.x - v00.x);
        float bot = v10.x + tx * (v11.x - v10.x);
        o.x = top + ty * (bot - top);
    }
    {
        float top = v00.y + tx * (v01.y - v00.y);
        float bot = v10.y + tx * (v11.y - v10.y);
        o.y = top + ty * (bot - top);
    }
    {
        float top = v00.z + tx * (v01.z - v00.z);
        float bot = v10.z + tx * (v11.z - v10.z);
        o.z = top + ty * (bot - top);
    }
    {
        float top = v00.w + tx * (v01.w - v00.w);
        float bot = v10.w + tx * (v11.w - v10.w);
        o.w = top + ty * (bot - top);
    }

    float4* out4 = (float4*)out;
    out4[((size_t)(roi * (POOL * POOL) + cell) << 8) + c] = o;
}

extern "C" void kernel_launch(void* const* d_in, const int* in_sizes, int n_in,
                              void* d_out, int out_size)
{
    const float* img  = (const float*)d_in[0];
    const float* rois = (const float*)d_in[1];
    float* out = (float*)d_out;

    dim3 grid(POOL * POOL, NUM_ROIS);
    roi_pool_kernel<<<grid, 256>>>(img, rois, out);
}